// round 11
// baseline (speedup 1.0000x reference)
#include <cuda_runtime.h>
#include <cuda_fp16.h>
#include <cstdint>

// ---------------------------------------------------------------------------
// UnpoolWithSkip — R8 GEMM shape (proven best: 128x128 tile, 256 thr, warp
// 32x64, 3-stage cp.async, ldmatrix, separate launches) + fp16 C scratch and
// fp16 fuse (traffic-positive deltas only). BN stats fp32 from accumulators.
// ---------------------------------------------------------------------------

#define EPS 1e-5f

static constexpr int N_IN  = 65536;
static constexpr int N_OUT = 262144;
static constexpr int C     = 256;

__device__ __half g_h[(size_t)N_IN  * C];
__device__ __half g_s[(size_t)N_OUT * C];
__device__ __half g_feat_h[(size_t)N_IN  * 512];
__device__ __half g_skip_h[(size_t)N_OUT * 256];
__device__ __half g_wt_proj[(size_t)C * 512];
__device__ __half g_wt_skip[(size_t)C * 256];
__device__ float g_sum_p[C], g_ssq_p[C];
__device__ float g_sum_s[C], g_ssq_s[C];
__device__ float g_a_p[C], g_b_p[C];
__device__ float g_a_s[C], g_b_s[C];

// ---------------------------------------------------------------------------
__device__ __forceinline__ void mma_f16(float* c, const uint32_t* a, const uint32_t* b) {
    asm volatile(
        "mma.sync.aligned.m16n8k16.row.col.f32.f16.f16.f32 "
        "{%0,%1,%2,%3}, {%4,%5,%6,%7}, {%8,%9}, {%0,%1,%2,%3};"
        : "+f"(c[0]), "+f"(c[1]), "+f"(c[2]), "+f"(c[3])
        : "r"(a[0]), "r"(a[1]), "r"(a[2]), "r"(a[3]), "r"(b[0]), "r"(b[1]));
}
__device__ __forceinline__ void ldsm_x4(uint32_t& d0, uint32_t& d1,
                                        uint32_t& d2, uint32_t& d3, uint32_t addr) {
    asm volatile("ldmatrix.sync.aligned.m8n8.x4.shared.b16 {%0,%1,%2,%3}, [%4];"
                 : "=r"(d0), "=r"(d1), "=r"(d2), "=r"(d3) : "r"(addr));
}
__device__ __forceinline__ uint32_t smem_u32(const void* p) {
    uint32_t a;
    asm("{ .reg .u64 t; cvta.to.shared.u64 t, %1; cvt.u32.u64 %0, t; }"
        : "=r"(a) : "l"(p));
    return a;
}

// ---------------------------------------------------------------------------
__global__ void zero_stats_kernel() {
    int c = threadIdx.x;
    g_sum_p[c] = 0.f; g_ssq_p[c] = 0.f;
    g_sum_s[c] = 0.f; g_ssq_s[c] = 0.f;
}

__global__ __launch_bounds__(256) void f2h_kernel(
    const float* __restrict__ src, __half* __restrict__ dst)
{
    size_t i = ((size_t)blockIdx.x * 256 + threadIdx.x) * 8;
    float4 a = *(const float4*)(src + i);
    float4 b = *(const float4*)(src + i + 4);
    __half2 h[4];
    h[0] = __floats2half2_rn(a.x, a.y);
    h[1] = __floats2half2_rn(a.z, a.w);
    h[2] = __floats2half2_rn(b.x, b.y);
    h[3] = __floats2half2_rn(b.z, b.w);
    *(uint4*)(dst + i) = *(uint4*)h;
}

__global__ void transpose_w_kernel(const float* __restrict__ W,
                                   __half* __restrict__ Wt, int K, int N) {
    __shared__ float t[32][33];
    int n0 = blockIdx.x * 32, k0 = blockIdx.y * 32;
    int tx = threadIdx.x, ty = threadIdx.y;
    #pragma unroll
    for (int i = 0; i < 32; i += 8)
        t[ty + i][tx] = W[(size_t)(k0 + ty + i) * N + n0 + tx];
    __syncthreads();
    #pragma unroll
    for (int i = 0; i < 32; i += 8)
        Wt[(size_t)(n0 + ty + i) * K + k0 + tx] = __float2half_rn(t[tx][ty + i]);
}

__global__ void finalize_kernel(
    const float* __restrict__ gamma_p, const float* __restrict__ beta_p,
    const float* __restrict__ gamma_s, const float* __restrict__ beta_s)
{
    int c = threadIdx.x;
    {
        float m = g_sum_p[c] * (1.f / N_IN);
        float v = g_ssq_p[c] * (1.f / N_IN) - m * m;
        float a = gamma_p[c] * rsqrtf(v + EPS);
        g_a_p[c] = a; g_b_p[c] = beta_p[c] - m * a;
    }
    {
        float m = g_sum_s[c] * (1.f / N_OUT);
        float v = g_ssq_s[c] * (1.f / N_OUT) - m * m;
        float a = gamma_s[c] * rsqrtf(v + EPS);
        g_a_s[c] = a; g_b_s[c] = beta_s[c] - m * a;
    }
}

// out[n,c] from fp16 h/s scratch; 8 channels per thread.
__global__ __launch_bounds__(256) void fuse_out_kernel(
    const int* __restrict__ cluster, float* __restrict__ out)
{
    int idx = blockIdx.x * 256 + threadIdx.x;     // N_OUT * 32 threads
    int n  = idx >> 5;
    int c8 = (idx & 31) << 3;
    int k  = __ldg(&cluster[n]);

    uint4 hraw = *(const uint4*)&g_h[(size_t)k * C + c8];
    uint4 sraw = *(const uint4*)&g_s[(size_t)n * C + c8];
    const __half2* hh = (const __half2*)&hraw;
    const __half2* ss = (const __half2*)&sraw;

    float4 o[2];
    #pragma unroll
    for (int q = 0; q < 4; q++) {
        int c2 = c8 + q * 2;
        float2 hv = __half22float2(hh[q]);
        float2 sv = __half22float2(ss[q]);
        ((float*)o)[q * 2] =
            fmaxf(fmaf(g_a_p[c2],     hv.x, g_b_p[c2]),     0.f)
          + fmaxf(fmaf(g_a_s[c2],     sv.x, g_b_s[c2]),     0.f);
        ((float*)o)[q * 2 + 1] =
            fmaxf(fmaf(g_a_p[c2 + 1], hv.y, g_b_p[c2 + 1]), 0.f)
          + fmaxf(fmaf(g_a_s[c2 + 1], sv.y, g_b_s[c2 + 1]), 0.f);
    }
    *(float4*)&out[(size_t)n * C + c8]     = o[0];
    *(float4*)&out[(size_t)n * C + c8 + 4] = o[1];
}

// ---------------------------------------------------------------------------
// fp16 GEMM: C[M,256] = A[M,K] @ Bt[256,K]^T + bias (fp32 acc), fp16 C out,
// + per-channel fp32 sum/sumsq. Tile 128x128, BK=64 halfs, 256 threads
// (warps 4m x 2n -> 32x64), 3-stage cp.async, ldmatrix. Grid (M/128, 2).
// ---------------------------------------------------------------------------
static constexpr int PAD_HALFS = 72;
static constexpr int PAD_BYTES = PAD_HALFS * 2;        // 144
static constexpr uint32_t A_BYTES = 128 * PAD_BYTES;   // 18432
static constexpr uint32_t STAGE_BYTES = A_BYTES * 2;
static constexpr int STAGES = 3;
static constexpr uint32_t SMEM_BYTES = STAGE_BYTES * STAGES;  // 110,592 B

__device__ __forceinline__ void load_tile_async(
    const __half* __restrict__ A, const __half* __restrict__ Bt, int K,
    int m0, int n0, int kt, uint32_t sbase, int tid)
{
    #pragma unroll
    for (int p = 0; p < 4; p++) {
        int idx = tid + p * 256;
        int row = idx >> 3, ch = idx & 7;
        const __half* ga = A + (size_t)(m0 + row) * K + kt * 64 + ch * 8;
        uint32_t sa = sbase + row * PAD_BYTES + ch * 16;
        asm volatile("cp.async.cg.shared.global [%0], [%1], 16;"
                     :: "r"(sa), "l"(ga) : "memory");
        const __half* gb = Bt + (size_t)(n0 + row) * K + kt * 64 + ch * 8;
        uint32_t sb = sbase + A_BYTES + row * PAD_BYTES + ch * 16;
        asm volatile("cp.async.cg.shared.global [%0], [%1], 16;"
                     :: "r"(sb), "l"(gb) : "memory");
    }
    asm volatile("cp.async.commit_group;" ::: "memory");
}

__global__ __launch_bounds__(256, 2) void mma_gemm_kernel(
    const __half* __restrict__ A, const __half* __restrict__ Bt,
    const float* __restrict__ bias, __half* __restrict__ Cout,
    int K, float* __restrict__ sum, float* __restrict__ ssq)
{
    extern __shared__ char smem_raw[];
    __shared__ float ssum[128], sssq[128];

    const int tid  = threadIdx.x;
    const int lane = tid & 31;
    const int wid  = tid >> 5;
    const int wm   = wid & 3;
    const int wn   = wid >> 2;
    const int g    = lane >> 2;
    const int t    = lane & 3;

    const int m0 = blockIdx.x * 128;
    const int n0 = blockIdx.y * 128;

    const uint32_t sbase = smem_u32(smem_raw);

    if (tid < 128) { ssum[tid] = 0.f; sssq[tid] = 0.f; }

    float acc[2][8][4];
    #pragma unroll
    for (int i = 0; i < 2; i++)
        #pragma unroll
        for (int j = 0; j < 8; j++)
            #pragma unroll
            for (int q = 0; q < 4; q++) acc[i][j][q] = 0.f;

    const int KT = K >> 6;            // BK = 64 halfs
    const int mw = wm * 32;
    const int nw = wn * 64;

    const int lm = lane >> 3;
    const int lr = lane & 7;
    uint32_t a_off[2];
    #pragma unroll
    for (int i = 0; i < 2; i++)
        a_off[i] = (uint32_t)((mw + i * 16 + (lm & 1) * 8 + lr) * PAD_BYTES
                              + (lm >> 1) * 16);
    uint32_t b_off[4];
    #pragma unroll
    for (int p = 0; p < 4; p++)
        b_off[p] = A_BYTES
                 + (uint32_t)((nw + 16 * p + 8 * (lm >> 1) + lr) * PAD_BYTES
                              + (lm & 1) * 16);

    load_tile_async(A, Bt, K, m0, n0, 0, sbase, tid);
    load_tile_async(A, Bt, K, m0, n0, 1, sbase + STAGE_BYTES, tid);

    int buf = 0;
    for (int kt = 0; kt < KT; kt++) {
        if (kt >= KT - 2)
            asm volatile("cp.async.wait_group 0;" ::: "memory");
        else
            asm volatile("cp.async.wait_group 1;" ::: "memory");
        __syncthreads();

        if (kt + 2 < KT) {
            int nb = buf + 2; if (nb >= STAGES) nb -= STAGES;
            load_tile_async(A, Bt, K, m0, n0, kt + 2,
                            sbase + (uint32_t)nb * STAGE_BYTES, tid);
        }

        const uint32_t stg = sbase + (uint32_t)buf * STAGE_BYTES;

        #pragma unroll
        for (int ks = 0; ks < 4; ks++) {
            const uint32_t kb = ks * 32;
            uint32_t af[2][4];
            ldsm_x4(af[0][0], af[0][1], af[0][2], af[0][3], stg + a_off[0] + kb);
            ldsm_x4(af[1][0], af[1][1], af[1][2], af[1][3], stg + a_off[1] + kb);
            uint32_t bf[8][2];
            #pragma unroll
            for (int p = 0; p < 4; p++)
                ldsm_x4(bf[2*p][0], bf[2*p][1], bf[2*p+1][0], bf[2*p+1][1],
                        stg + b_off[p] + kb);
            #pragma unroll
            for (int i = 0; i < 2; i++)
                #pragma unroll
                for (int j = 0; j < 8; j++)
                    mma_f16(acc[i][j], af[i], bf[j]);
        }

        buf++; if (buf == STAGES) buf = 0;
    }
    __syncthreads();

    // ---- Epilogue: bias add, fp16 stores, fp32 BN stats ----
    #pragma unroll
    for (int j = 0; j < 8; j++) {
        const int cl = nw + j * 8 + 2 * t;
        const int cg = n0 + cl;
        const float b0v = __ldg(&bias[cg]);
        const float b1v = __ldg(&bias[cg + 1]);
        float s0 = 0.f, s1 = 0.f, q0 = 0.f, q1 = 0.f;
        #pragma unroll
        for (int i = 0; i < 2; i++) {
            const int row = m0 + mw + i * 16 + g;
            float v00 = acc[i][j][0] + b0v;
            float v01 = acc[i][j][1] + b1v;
            float v10 = acc[i][j][2] + b0v;
            float v11 = acc[i][j][3] + b1v;
            *(__half2*)&Cout[(size_t)row * C + cg]       = __floats2half2_rn(v00, v01);
            *(__half2*)&Cout[(size_t)(row + 8) * C + cg] = __floats2half2_rn(v10, v11);
            s0 += v00 + v10;  s1 += v01 + v11;
            q0 += v00 * v00 + v10 * v10;
            q1 += v01 * v01 + v11 * v11;
        }
        atomicAdd(&ssum[cl], s0);     atomicAdd(&ssum[cl + 1], s1);
        atomicAdd(&sssq[cl], q0);     atomicAdd(&sssq[cl + 1], q1);
    }
    __syncthreads();
    if (tid < 128) {
        atomicAdd(&sum[n0 + tid], ssum[tid]);
        atomicAdd(&ssq[n0 + tid], sssq[tid]);
    }
}

// ---------------------------------------------------------------------------
extern "C" void kernel_launch(void* const* d_in, const int* in_sizes, int n_in,
                              void* d_out, int out_size)
{
    const float* feat    = (const float*)d_in[0];
    const float* skip    = (const float*)d_in[1];
    const int*   cluster = (const int*)  d_in[2];
    const float* W_proj  = (const float*)d_in[3];
    const float* b_proj  = (const float*)d_in[4];
    const float* gamma_p = (const float*)d_in[5];
    const float* beta_p  = (const float*)d_in[6];
    const float* W_skip  = (const float*)d_in[7];
    const float* b_skip  = (const float*)d_in[8];
    const float* gamma_s = (const float*)d_in[9];
    const float* beta_s  = (const float*)d_in[10];
    float* out = (float*)d_out;

    float *sum_p, *ssq_p, *sum_s, *ssq_s;
    __half *h_ptr, *s_ptr, *feat_h, *skip_h, *wtp, *wts;
    cudaGetSymbolAddress((void**)&h_ptr, g_h);
    cudaGetSymbolAddress((void**)&s_ptr, g_s);
    cudaGetSymbolAddress((void**)&feat_h, g_feat_h);
    cudaGetSymbolAddress((void**)&skip_h, g_skip_h);
    cudaGetSymbolAddress((void**)&wtp, g_wt_proj);
    cudaGetSymbolAddress((void**)&wts, g_wt_skip);
    cudaGetSymbolAddress((void**)&sum_p, g_sum_p);
    cudaGetSymbolAddress((void**)&ssq_p, g_ssq_p);
    cudaGetSymbolAddress((void**)&sum_s, g_sum_s);
    cudaGetSymbolAddress((void**)&ssq_s, g_ssq_s);

    cudaFuncSetAttribute(mma_gemm_kernel,
                         cudaFuncAttributeMaxDynamicSharedMemorySize, SMEM_BYTES);

    zero_stats_kernel<<<1, 256>>>();

    f2h_kernel<<<(int)(((size_t)N_OUT * 256) / 2048), 256>>>(skip, skip_h);
    f2h_kernel<<<(int)(((size_t)N_IN * 512) / 2048), 256>>>(feat, feat_h);

    transpose_w_kernel<<<dim3(256 / 32, 512 / 32), dim3(32, 8)>>>(W_proj, wtp, 512, 256);
    transpose_w_kernel<<<dim3(256 / 32, 256 / 32), dim3(32, 8)>>>(W_skip, wts, 256, 256);

    // GEMM2 first (big), then GEMM1 so g_h stays L2-warm for the gather.
    mma_gemm_kernel<<<dim3(N_OUT / 128, 2), 256, SMEM_BYTES>>>(
        skip_h, wts, b_skip, s_ptr, 256, sum_s, ssq_s);

    mma_gemm_kernel<<<dim3(N_IN / 128, 2), 256, SMEM_BYTES>>>(
        feat_h, wtp, b_proj, h_ptr, 512, sum_p, ssq_p);

    finalize_kernel<<<1, 256>>>(gamma_p, beta_p, gamma_s, beta_s);

    fuse_out_kernel<<<N_OUT * 32 / 256, 256>>>(cluster, out);
}

// round 12
// speedup vs baseline: 1.2023x; 1.2023x over previous
#include <cuda_runtime.h>
#include <cuda_fp16.h>
#include <cstdint>

// ---------------------------------------------------------------------------
// UnpoolWithSkip — R8 configuration verbatim (fp16 m16n8k16 GEMMs, fp32 C
// scratch, fp32 fuse) with ONE change: GEMM grid is (2, M/128) so the two
// n-split CTAs sharing an A tile are adjacent bids -> co-resident -> the
// second A read hits L2 instead of DRAM.
// ---------------------------------------------------------------------------

#define EPS 1e-5f

static constexpr int N_IN  = 65536;
static constexpr int N_OUT = 262144;
static constexpr int C     = 256;

__device__ float  g_h[(size_t)N_IN  * C];
__device__ float  g_s[(size_t)N_OUT * C];
__device__ __half g_feat_h[(size_t)N_IN  * 512];
__device__ __half g_skip_h[(size_t)N_OUT * 256];
__device__ __half g_wt_proj[(size_t)C * 512];
__device__ __half g_wt_skip[(size_t)C * 256];
__device__ float g_sum_p[C], g_ssq_p[C];
__device__ float g_sum_s[C], g_ssq_s[C];
__device__ float g_a_p[C], g_b_p[C];
__device__ float g_a_s[C], g_b_s[C];

// ---------------------------------------------------------------------------
__device__ __forceinline__ void mma_f16(float* c, const uint32_t* a, const uint32_t* b) {
    asm volatile(
        "mma.sync.aligned.m16n8k16.row.col.f32.f16.f16.f32 "
        "{%0,%1,%2,%3}, {%4,%5,%6,%7}, {%8,%9}, {%0,%1,%2,%3};"
        : "+f"(c[0]), "+f"(c[1]), "+f"(c[2]), "+f"(c[3])
        : "r"(a[0]), "r"(a[1]), "r"(a[2]), "r"(a[3]), "r"(b[0]), "r"(b[1]));
}
__device__ __forceinline__ void ldsm_x4(uint32_t& d0, uint32_t& d1,
                                        uint32_t& d2, uint32_t& d3, uint32_t addr) {
    asm volatile("ldmatrix.sync.aligned.m8n8.x4.shared.b16 {%0,%1,%2,%3}, [%4];"
                 : "=r"(d0), "=r"(d1), "=r"(d2), "=r"(d3) : "r"(addr));
}
__device__ __forceinline__ uint32_t smem_u32(const void* p) {
    uint32_t a;
    asm("{ .reg .u64 t; cvta.to.shared.u64 t, %1; cvt.u32.u64 %0, t; }"
        : "=r"(a) : "l"(p));
    return a;
}

// ---------------------------------------------------------------------------
__global__ void zero_stats_kernel() {
    int c = threadIdx.x;
    g_sum_p[c] = 0.f; g_ssq_p[c] = 0.f;
    g_sum_s[c] = 0.f; g_ssq_s[c] = 0.f;
}

__global__ __launch_bounds__(256) void f2h_kernel(
    const float* __restrict__ src, __half* __restrict__ dst)
{
    size_t i = ((size_t)blockIdx.x * 256 + threadIdx.x) * 8;
    float4 a = *(const float4*)(src + i);
    float4 b = *(const float4*)(src + i + 4);
    __half2 h[4];
    h[0] = __floats2half2_rn(a.x, a.y);
    h[1] = __floats2half2_rn(a.z, a.w);
    h[2] = __floats2half2_rn(b.x, b.y);
    h[3] = __floats2half2_rn(b.z, b.w);
    *(uint4*)(dst + i) = *(uint4*)h;
}

__global__ void transpose_w_kernel(const float* __restrict__ W,
                                   __half* __restrict__ Wt, int K, int N) {
    __shared__ float t[32][33];
    int n0 = blockIdx.x * 32, k0 = blockIdx.y * 32;
    int tx = threadIdx.x, ty = threadIdx.y;
    #pragma unroll
    for (int i = 0; i < 32; i += 8)
        t[ty + i][tx] = W[(size_t)(k0 + ty + i) * N + n0 + tx];
    __syncthreads();
    #pragma unroll
    for (int i = 0; i < 32; i += 8)
        Wt[(size_t)(n0 + ty + i) * K + k0 + tx] = __float2half_rn(t[tx][ty + i]);
}

__global__ void finalize_kernel(
    const float* __restrict__ gamma_p, const float* __restrict__ beta_p,
    const float* __restrict__ gamma_s, const float* __restrict__ beta_s)
{
    int c = threadIdx.x;
    {
        float m = g_sum_p[c] * (1.f / N_IN);
        float v = g_ssq_p[c] * (1.f / N_IN) - m * m;
        float a = gamma_p[c] * rsqrtf(v + EPS);
        g_a_p[c] = a; g_b_p[c] = beta_p[c] - m * a;
    }
    {
        float m = g_sum_s[c] * (1.f / N_OUT);
        float v = g_ssq_s[c] * (1.f / N_OUT) - m * m;
        float a = gamma_s[c] * rsqrtf(v + EPS);
        g_a_s[c] = a; g_b_s[c] = beta_s[c] - m * a;
    }
}

__global__ __launch_bounds__(256) void fuse_out_kernel(
    const int* __restrict__ cluster, float* __restrict__ out)
{
    int idx = blockIdx.x * 256 + threadIdx.x;
    int n  = idx >> 6;
    int c4 = (idx & 63) << 2;
    int k  = __ldg(&cluster[n]);

    float4 h  = *(const float4*)&g_h[(size_t)k * C + c4];
    float4 sv = *(const float4*)&g_s[(size_t)n * C + c4];
    float4 ap = *(const float4*)&g_a_p[c4];
    float4 bp = *(const float4*)&g_b_p[c4];
    float4 as_ = *(const float4*)&g_a_s[c4];
    float4 bs_ = *(const float4*)&g_b_s[c4];

    float4 o;
    o.x = fmaxf(fmaf(ap.x, h.x, bp.x), 0.f) + fmaxf(fmaf(as_.x, sv.x, bs_.x), 0.f);
    o.y = fmaxf(fmaf(ap.y, h.y, bp.y), 0.f) + fmaxf(fmaf(as_.y, sv.y, bs_.y), 0.f);
    o.z = fmaxf(fmaf(ap.z, h.z, bp.z), 0.f) + fmaxf(fmaf(as_.z, sv.z, bs_.z), 0.f);
    o.w = fmaxf(fmaf(ap.w, h.w, bp.w), 0.f) + fmaxf(fmaf(as_.w, sv.w, bs_.w), 0.f);
    *(float4*)&out[(size_t)n * C + c4] = o;
}

// ---------------------------------------------------------------------------
// fp16 GEMM: C[M,256] = A[M,K] @ Bt[256,K]^T + bias (fp32 acc, fp32 C out),
// + per-channel fp32 sum/sumsq. Tile 128x128, BK=64 halfs, 256 threads
// (warps 4m x 2n -> 32x64), 3-stage cp.async, ldmatrix.
// Grid (2, M/128): n-split pairs adjacent -> A tile L2 reuse.
// ---------------------------------------------------------------------------
static constexpr int PAD_HALFS = 72;
static constexpr int PAD_BYTES = PAD_HALFS * 2;        // 144
static constexpr uint32_t A_BYTES = 128 * PAD_BYTES;   // 18432
static constexpr uint32_t STAGE_BYTES = A_BYTES * 2;
static constexpr int STAGES = 3;
static constexpr uint32_t SMEM_BYTES = STAGE_BYTES * STAGES;  // 110,592 B

__device__ __forceinline__ void load_tile_async(
    const __half* __restrict__ A, const __half* __restrict__ Bt, int K,
    int m0, int n0, int kt, uint32_t sbase, int tid)
{
    #pragma unroll
    for (int p = 0; p < 4; p++) {
        int idx = tid + p * 256;
        int row = idx >> 3, ch = idx & 7;
        const __half* ga = A + (size_t)(m0 + row) * K + kt * 64 + ch * 8;
        uint32_t sa = sbase + row * PAD_BYTES + ch * 16;
        asm volatile("cp.async.cg.shared.global [%0], [%1], 16;"
                     :: "r"(sa), "l"(ga) : "memory");
        const __half* gb = Bt + (size_t)(n0 + row) * K + kt * 64 + ch * 8;
        uint32_t sb = sbase + A_BYTES + row * PAD_BYTES + ch * 16;
        asm volatile("cp.async.cg.shared.global [%0], [%1], 16;"
                     :: "r"(sb), "l"(gb) : "memory");
    }
    asm volatile("cp.async.commit_group;" ::: "memory");
}

__global__ __launch_bounds__(256) void mma_gemm_kernel(
    const __half* __restrict__ A, const __half* __restrict__ Bt,
    const float* __restrict__ bias, float* __restrict__ Cout,
    int K, float* __restrict__ sum, float* __restrict__ ssq)
{
    extern __shared__ char smem_raw[];
    __shared__ float ssum[128], sssq[128];

    const int tid  = threadIdx.x;
    const int lane = tid & 31;
    const int wid  = tid >> 5;
    const int wm   = wid & 3;
    const int wn   = wid >> 2;
    const int g    = lane >> 2;
    const int t    = lane & 3;

    const int n0 = blockIdx.x * 128;     // n-split: adjacent bids share A
    const int m0 = blockIdx.y * 128;

    const uint32_t sbase = smem_u32(smem_raw);

    if (tid < 128) { ssum[tid] = 0.f; sssq[tid] = 0.f; }

    float acc[2][8][4];
    #pragma unroll
    for (int i = 0; i < 2; i++)
        #pragma unroll
        for (int j = 0; j < 8; j++)
            #pragma unroll
            for (int q = 0; q < 4; q++) acc[i][j][q] = 0.f;

    const int KT = K >> 6;            // BK = 64 halfs
    const int mw = wm * 32;
    const int nw = wn * 64;

    const int lm = lane >> 3;
    const int lr = lane & 7;
    uint32_t a_off[2];
    #pragma unroll
    for (int i = 0; i < 2; i++)
        a_off[i] = (uint32_t)((mw + i * 16 + (lm & 1) * 8 + lr) * PAD_BYTES
                              + (lm >> 1) * 16);
    uint32_t b_off[4];
    #pragma unroll
    for (int p = 0; p < 4; p++)
        b_off[p] = A_BYTES
                 + (uint32_t)((nw + 16 * p + 8 * (lm >> 1) + lr) * PAD_BYTES
                              + (lm & 1) * 16);

    load_tile_async(A, Bt, K, m0, n0, 0, sbase, tid);
    load_tile_async(A, Bt, K, m0, n0, 1, sbase + STAGE_BYTES, tid);

    int buf = 0;
    for (int kt = 0; kt < KT; kt++) {
        if (kt >= KT - 2)
            asm volatile("cp.async.wait_group 0;" ::: "memory");
        else
            asm volatile("cp.async.wait_group 1;" ::: "memory");
        __syncthreads();

        if (kt + 2 < KT) {
            int nb = buf + 2; if (nb >= STAGES) nb -= STAGES;
            load_tile_async(A, Bt, K, m0, n0, kt + 2,
                            sbase + (uint32_t)nb * STAGE_BYTES, tid);
        }

        const uint32_t stg = sbase + (uint32_t)buf * STAGE_BYTES;

        #pragma unroll
        for (int ks = 0; ks < 4; ks++) {
            const uint32_t kb = ks * 32;
            uint32_t af[2][4];
            ldsm_x4(af[0][0], af[0][1], af[0][2], af[0][3], stg + a_off[0] + kb);
            ldsm_x4(af[1][0], af[1][1], af[1][2], af[1][3], stg + a_off[1] + kb);
            uint32_t bf[8][2];
            #pragma unroll
            for (int p = 0; p < 4; p++)
                ldsm_x4(bf[2*p][0], bf[2*p][1], bf[2*p+1][0], bf[2*p+1][1],
                        stg + b_off[p] + kb);
            #pragma unroll
            for (int i = 0; i < 2; i++)
                #pragma unroll
                for (int j = 0; j < 8; j++)
                    mma_f16(acc[i][j], af[i], bf[j]);
        }

        buf++; if (buf == STAGES) buf = 0;
    }
    __syncthreads();

    // ---- Epilogue: bias add, float2 stores, fp32 BN stats ----
    #pragma unroll
    for (int j = 0; j < 8; j++) {
        const int cl = nw + j * 8 + 2 * t;
        const int cg = n0 + cl;
        const float b0v = __ldg(&bias[cg]);
        const float b1v = __ldg(&bias[cg + 1]);
        float s0 = 0.f, s1 = 0.f, q0 = 0.f, q1 = 0.f;
        #pragma unroll
        for (int i = 0; i < 2; i++) {
            const int row = m0 + mw + i * 16 + g;
            float v00 = acc[i][j][0] + b0v;
            float v01 = acc[i][j][1] + b1v;
            float v10 = acc[i][j][2] + b0v;
            float v11 = acc[i][j][3] + b1v;
            float2 lo; lo.x = v00; lo.y = v01;
            float2 hi; hi.x = v10; hi.y = v11;
            *(float2*)&Cout[(size_t)row * C + cg] = lo;
            *(float2*)&Cout[(size_t)(row + 8) * C + cg] = hi;
            s0 += v00 + v10;  s1 += v01 + v11;
            q0 += v00 * v00 + v10 * v10;
            q1 += v01 * v01 + v11 * v11;
        }
        atomicAdd(&ssum[cl], s0);     atomicAdd(&ssum[cl + 1], s1);
        atomicAdd(&sssq[cl], q0);     atomicAdd(&sssq[cl + 1], q1);
    }
    __syncthreads();
    if (tid < 128) {
        atomicAdd(&sum[n0 + tid], ssum[tid]);
        atomicAdd(&ssq[n0 + tid], sssq[tid]);
    }
}

// ---------------------------------------------------------------------------
extern "C" void kernel_launch(void* const* d_in, const int* in_sizes, int n_in,
                              void* d_out, int out_size)
{
    const float* feat    = (const float*)d_in[0];
    const float* skip    = (const float*)d_in[1];
    const int*   cluster = (const int*)  d_in[2];
    const float* W_proj  = (const float*)d_in[3];
    const float* b_proj  = (const float*)d_in[4];
    const float* gamma_p = (const float*)d_in[5];
    const float* beta_p  = (const float*)d_in[6];
    const float* W_skip  = (const float*)d_in[7];
    const float* b_skip  = (const float*)d_in[8];
    const float* gamma_s = (const float*)d_in[9];
    const float* beta_s  = (const float*)d_in[10];
    float* out = (float*)d_out;

    float *h_ptr, *s_ptr, *sum_p, *ssq_p, *sum_s, *ssq_s;
    __half *feat_h, *skip_h, *wtp, *wts;
    cudaGetSymbolAddress((void**)&h_ptr, g_h);
    cudaGetSymbolAddress((void**)&s_ptr, g_s);
    cudaGetSymbolAddress((void**)&feat_h, g_feat_h);
    cudaGetSymbolAddress((void**)&skip_h, g_skip_h);
    cudaGetSymbolAddress((void**)&wtp, g_wt_proj);
    cudaGetSymbolAddress((void**)&wts, g_wt_skip);
    cudaGetSymbolAddress((void**)&sum_p, g_sum_p);
    cudaGetSymbolAddress((void**)&ssq_p, g_ssq_p);
    cudaGetSymbolAddress((void**)&sum_s, g_sum_s);
    cudaGetSymbolAddress((void**)&ssq_s, g_ssq_s);

    cudaFuncSetAttribute(mma_gemm_kernel,
                         cudaFuncAttributeMaxDynamicSharedMemorySize, SMEM_BYTES);

    zero_stats_kernel<<<1, 256>>>();

    f2h_kernel<<<(int)(((size_t)N_OUT * 256) / 2048), 256>>>(skip, skip_h);
    f2h_kernel<<<(int)(((size_t)N_IN * 512) / 2048), 256>>>(feat, feat_h);

    transpose_w_kernel<<<dim3(256 / 32, 512 / 32), dim3(32, 8)>>>(W_proj, wtp, 512, 256);
    transpose_w_kernel<<<dim3(256 / 32, 256 / 32), dim3(32, 8)>>>(W_skip, wts, 256, 256);

    // GEMM2 first (big), then GEMM1 so g_h stays L2-warm for the gather.
    mma_gemm_kernel<<<dim3(2, N_OUT / 128), 256, SMEM_BYTES>>>(
        skip_h, wts, b_skip, s_ptr, 256, sum_s, ssq_s);

    mma_gemm_kernel<<<dim3(2, N_IN / 128), 256, SMEM_BYTES>>>(
        feat_h, wtp, b_proj, h_ptr, 512, sum_p, ssq_p);

    finalize_kernel<<<1, 256>>>(gamma_p, beta_p, gamma_s, beta_s);

    fuse_out_kernel<<<(N_OUT * 64) / 256, 256>>>(cluster, out);
}